// round 2
// baseline (speedup 1.0000x reference)
#include <cuda_runtime.h>
#include <cuda_bf16.h>
#include <math.h>

#define S_TOK 4096
#define D_DIM 2048

// ---------------- scratch (no allocation allowed -> __device__ globals) ----------
__device__ float g_q[(size_t)S_TOK * D_DIM];        // 32 MB
__device__ float g_k[(size_t)S_TOK * D_DIM];        // 32 MB
__device__ float g_v[(size_t)S_TOK * D_DIM];        // 32 MB
__device__ float g_scores[(size_t)S_TOK * S_TOK];   // 64 MB

// =================================================================================
// NT SGEMM: C[M,N] = A[M,K] * B[N,K]^T
// A row-major lda=K, B row-major ldb=K, C row-major ldc=N.
// BM=BN=64, BK=16, 256 threads, 4x4 per thread.
// causal!=0: skip blocks entirely above the diagonal (n0 >= m0+BM).
// =================================================================================
__global__ __launch_bounds__(256) void sgemm_nt(
    const float* __restrict__ A, const float* __restrict__ B, float* __restrict__ C,
    int M, int N, int K, int causal)
{
    const int BM = 64, BN = 64, BK = 16;
    __shared__ float As[BK][BM + 4];
    __shared__ float Bs[BK][BN + 4];

    const int m0 = blockIdx.y * BM;
    const int n0 = blockIdx.x * BN;
    if (causal && n0 >= m0 + BM) return;   // fully above diagonal -> never read

    const int tid = threadIdx.x;
    const int tx = tid & 15;       // 0..15 -> C cols
    const int ty = tid >> 4;       // 0..15 -> C rows
    const int lrow = tid >> 2;     // 0..63  load row
    const int lseg = tid & 3;      // 0..3   load 4-float segment

    float acc[4][4] = {};

    const float* aptr = A + (size_t)(m0 + lrow) * K + lseg * 4;
    const float* bptr = B + (size_t)(n0 + lrow) * K + lseg * 4;

    for (int k0 = 0; k0 < K; k0 += BK) {
        float4 a = *(const float4*)(aptr + k0);
        float4 b = *(const float4*)(bptr + k0);
        As[lseg * 4 + 0][lrow] = a.x;
        As[lseg * 4 + 1][lrow] = a.y;
        As[lseg * 4 + 2][lrow] = a.z;
        As[lseg * 4 + 3][lrow] = a.w;
        Bs[lseg * 4 + 0][lrow] = b.x;
        Bs[lseg * 4 + 1][lrow] = b.y;
        Bs[lseg * 4 + 2][lrow] = b.z;
        Bs[lseg * 4 + 3][lrow] = b.w;
        __syncthreads();

        #pragma unroll
        for (int kk = 0; kk < BK; kk++) {
            float4 ra = *(const float4*)&As[kk][ty * 4];
            float4 rb = *(const float4*)&Bs[kk][tx * 4];
            float av[4] = {ra.x, ra.y, ra.z, ra.w};
            float bv[4] = {rb.x, rb.y, rb.z, rb.w};
            #pragma unroll
            for (int i = 0; i < 4; i++)
                #pragma unroll
                for (int j = 0; j < 4; j++)
                    acc[i][j] = fmaf(av[i], bv[j], acc[i][j]);
        }
        __syncthreads();
    }

    #pragma unroll
    for (int i = 0; i < 4; i++) {
        float* crow = C + (size_t)(m0 + ty * 4 + i) * N + n0 + tx * 4;
        #pragma unroll
        for (int j = 0; j < 4; j++) crow[j] = acc[i][j];
    }
}

// =================================================================================
// NN SGEMM (triangular k-range): C[M,N] = A[M,K] * B[K,N], k in [0, m0+BM)
// Used for out = attn @ V. attn rows are zero-padded up to the 64-boundary
// past the diagonal, so bounding k at the row-block end is exact.
// =================================================================================
__global__ __launch_bounds__(256) void sgemm_nn_tri(
    const float* __restrict__ A, const float* __restrict__ B, float* __restrict__ C,
    int M, int N, int K)
{
    const int BM = 64, BN = 64, BK = 16;
    __shared__ float As[BK][BM + 4];
    __shared__ float Bs[BK][BN + 4];

    const int m0 = blockIdx.y * BM;
    const int n0 = blockIdx.x * BN;

    const int tid = threadIdx.x;
    const int tx = tid & 15;
    const int ty = tid >> 4;
    const int lrow = tid >> 2;     // A: 0..63 row
    const int lseg = tid & 3;      // A: segment
    const int bkr = tid >> 4;      // B: 0..15 k-row
    const int bnc = (tid & 15) * 4;// B: col

    float acc[4][4] = {};

    const int kend = min(K, m0 + BM);   // causal bound

    for (int k0 = 0; k0 < kend; k0 += BK) {
        float4 a = *(const float4*)(A + (size_t)(m0 + lrow) * K + k0 + lseg * 4);
        float4 b = *(const float4*)(B + (size_t)(k0 + bkr) * N + n0 + bnc);
        As[lseg * 4 + 0][lrow] = a.x;
        As[lseg * 4 + 1][lrow] = a.y;
        As[lseg * 4 + 2][lrow] = a.z;
        As[lseg * 4 + 3][lrow] = a.w;
        *(float4*)&Bs[bkr][bnc] = b;
        __syncthreads();

        #pragma unroll
        for (int kk = 0; kk < BK; kk++) {
            float4 ra = *(const float4*)&As[kk][ty * 4];
            float4 rb = *(const float4*)&Bs[kk][tx * 4];
            float av[4] = {ra.x, ra.y, ra.z, ra.w};
            float bv[4] = {rb.x, rb.y, rb.z, rb.w};
            #pragma unroll
            for (int i = 0; i < 4; i++)
                #pragma unroll
                for (int j = 0; j < 4; j++)
                    acc[i][j] = fmaf(av[i], bv[j], acc[i][j]);
        }
        __syncthreads();
    }

    #pragma unroll
    for (int i = 0; i < 4; i++) {
        float* crow = C + (size_t)(m0 + ty * 4 + i) * N + n0 + tx * 4;
        #pragma unroll
        for (int j = 0; j < 4; j++) crow[j] = acc[i][j];
    }
}

// =================================================================================
// Row softmax (causal, scaled) + dropout mask, in place on g_scores.
// Row i: valid j in [0, i]. Writes attn = exp(s*scale - m)/Z * mask for j<=i,
// zeros for j in (i, 64-aligned block end). Columns beyond that are never read.
// =================================================================================
__global__ __launch_bounds__(256) void softmax_dropout_kernel(
    float* __restrict__ scores, const float* __restrict__ drop_mask)
{
    const int i = blockIdx.x;
    const int tid = threadIdx.x;
    const int nvalid = i + 1;
    const float scale = rsqrtf((float)D_DIM);

    float* row = scores + (size_t)i * S_TOK;
    const float* mrow = drop_mask + (size_t)i * S_TOK;

    __shared__ float red[256];

    // pass 1: max of scaled logits
    float lmax = -INFINITY;
    for (int j = tid; j < nvalid; j += 256) lmax = fmaxf(lmax, row[j] * scale);
    red[tid] = lmax;
    __syncthreads();
    for (int s = 128; s > 0; s >>= 1) {
        if (tid < s) red[tid] = fmaxf(red[tid], red[tid + s]);
        __syncthreads();
    }
    const float m = red[0];
    __syncthreads();

    // pass 2: sum of exp
    float lsum = 0.f;
    for (int j = tid; j < nvalid; j += 256) lsum += __expf(row[j] * scale - m);
    red[tid] = lsum;
    __syncthreads();
    for (int s = 128; s > 0; s >>= 1) {
        if (tid < s) red[tid] += red[tid + s];
        __syncthreads();
    }
    const float inv_z = 1.0f / red[0];

    // pass 3: write normalized * dropout; zero-pad to the 64-aligned block end
    const int zend = min(S_TOK, ((i >> 6) + 1) << 6);
    for (int j = tid; j < zend; j += 256) {
        float out = 0.f;
        if (j < nvalid) out = __expf(row[j] * scale - m) * inv_z * mrow[j];
        row[j] = out;
    }
}

// =================================================================================
// launch
// =================================================================================
extern "C" void kernel_launch(void* const* d_in, const int* in_sizes, int n_in,
                              void* d_out, int out_size)
{
    const float* x  = (const float*)d_in[0];   // [S, D]
    const float* Wq = (const float*)d_in[1];   // [D, D]
    const float* Wk = (const float*)d_in[2];
    const float* Wv = (const float*)d_in[3];
    const float* dm = (const float*)d_in[4];   // [S, S]
    float* out = (float*)d_out;                // [S, D]

    float *q, *k, *v, *sc;
    cudaGetSymbolAddress((void**)&q,  g_q);
    cudaGetSymbolAddress((void**)&k,  g_k);
    cudaGetSymbolAddress((void**)&v,  g_v);
    cudaGetSymbolAddress((void**)&sc, g_scores);

    // 1) Q/K/V projections: q = x @ W^T  (NT gemm, M=S, N=D, K=D)
    dim3 gProj(D_DIM / 64, S_TOK / 64);
    sgemm_nt<<<gProj, 256>>>(x, Wq, q, S_TOK, D_DIM, D_DIM, 0);
    sgemm_nt<<<gProj, 256>>>(x, Wk, k, S_TOK, D_DIM, D_DIM, 0);
    sgemm_nt<<<gProj, 256>>>(x, Wv, v, S_TOK, D_DIM, D_DIM, 0);

    // 2) scores = q @ k^T (causal: skip above-diagonal blocks)
    dim3 gScore(S_TOK / 64, S_TOK / 64);
    sgemm_nt<<<gScore, 256>>>(q, k, sc, S_TOK, S_TOK, D_DIM, 1);

    // 3) softmax(scale) + dropout, in place, with zero-pad to 64-block boundary
    softmax_dropout_kernel<<<S_TOK, 256>>>(sc, dm);

    // 4) out = attn @ v (NN gemm, k bounded by causal row-block end)
    dim3 gOut(D_DIM / 64, S_TOK / 64);
    sgemm_nn_tri<<<gOut, 256>>>(sc, v, out, S_TOK, D_DIM, S_TOK);
}

// round 4
// speedup vs baseline: 3.3684x; 3.3684x over previous
#include <cuda_runtime.h>
#include <cuda_bf16.h>
#include <math.h>
#include <stdint.h>

#define S_TOK 4096
#define D_DIM 2048

// ---------------- scratch (no allocation allowed -> __device__ globals) ----------
__device__ __nv_bfloat16 g_xh[(size_t)S_TOK * D_DIM];
__device__ __nv_bfloat16 g_xl[(size_t)S_TOK * D_DIM];
__device__ __nv_bfloat16 g_wqh[(size_t)D_DIM * D_DIM];
__device__ __nv_bfloat16 g_wql[(size_t)D_DIM * D_DIM];
__device__ __nv_bfloat16 g_wkh[(size_t)D_DIM * D_DIM];
__device__ __nv_bfloat16 g_wkl[(size_t)D_DIM * D_DIM];
__device__ __nv_bfloat16 g_wvh[(size_t)D_DIM * D_DIM];
__device__ __nv_bfloat16 g_wvl[(size_t)D_DIM * D_DIM];
__device__ __nv_bfloat16 g_qh[(size_t)S_TOK * D_DIM];
__device__ __nv_bfloat16 g_ql[(size_t)S_TOK * D_DIM];
__device__ __nv_bfloat16 g_kh[(size_t)S_TOK * D_DIM];
__device__ __nv_bfloat16 g_kl[(size_t)S_TOK * D_DIM];
__device__ __nv_bfloat16 g_vth[(size_t)D_DIM * S_TOK];   // vT [D, S]
__device__ __nv_bfloat16 g_vtl[(size_t)D_DIM * S_TOK];
__device__ float         g_sc[(size_t)S_TOK * S_TOK];    // scores fp32
__device__ __nv_bfloat16 g_ah[(size_t)S_TOK * S_TOK];    // attn hi
__device__ __nv_bfloat16 g_al[(size_t)S_TOK * S_TOK];    // attn lo

// ============================ PTX helpers (base-arch only) ========================
__device__ __forceinline__ uint32_t smem_u32(const void* p) {
    uint32_t a;
    asm("{ .reg .u64 t; cvta.to.shared.u64 t, %1; cvt.u32.u64 %0, t; }" : "=r"(a) : "l"(p));
    return a;
}
#define CP_ASYNC16(dst, src) \
    asm volatile("cp.async.cg.shared.global [%0], [%1], 16;" :: "r"(dst), "l"(src) : "memory")
#define CP_COMMIT() asm volatile("cp.async.commit_group;" ::: "memory")
#define CP_WAIT1()  asm volatile("cp.async.wait_group 1;" ::: "memory")
#define CP_WAIT0()  asm volatile("cp.async.wait_group 0;" ::: "memory")

__device__ __forceinline__ void ldsm_x4(uint32_t addr, uint32_t* r) {
    asm volatile("ldmatrix.sync.aligned.m8n8.x4.shared.b16 {%0,%1,%2,%3}, [%4];"
                 : "=r"(r[0]), "=r"(r[1]), "=r"(r[2]), "=r"(r[3]) : "r"(addr));
}
__device__ __forceinline__ void mma_bf16(float* d, const uint32_t* a, const uint32_t* b) {
    asm volatile(
        "mma.sync.aligned.m16n8k16.row.col.f32.bf16.bf16.f32 "
        "{%0,%1,%2,%3}, {%4,%5,%6,%7}, {%8,%9}, {%0,%1,%2,%3};"
        : "+f"(d[0]), "+f"(d[1]), "+f"(d[2]), "+f"(d[3])
        : "r"(a[0]), "r"(a[1]), "r"(a[2]), "r"(a[3]), "r"(b[0]), "r"(b[1]));
}
__device__ __forceinline__ uint32_t sw128(uint32_t off) { return off ^ ((off >> 3) & 0x70); }

// ============================ bf16 split-precision NT GEMM ========================
// C[M,N] = (Ah+Al)[M,K] * (Bh+Bl)[N,K]^T  (drop Al*Bl). Tile 128x128, K-chunk 64.
// mode: 0 full, 1 causal tile-skip (nb > mb), 2 triangular K (kend = m0+128)
// epi:  0 write fp32 C, 1 write hi/lo bf16 (Ch, Cl)
// smem: 2 buffers x (Ah,Al,Bh,Bl each 128x64bf16 = 16KB) = 128KB, SW128 swizzle.
#define TILE_B   16384
#define BUF_B    (4 * TILE_B)
#define GEMM_SMEM (2 * BUF_B)

__device__ __forceinline__ void issue_tile64(const __nv_bfloat16* __restrict__ g,
                                             int row0, int ld, int k0,
                                             uint32_t sbase, int tid) {
    #pragma unroll
    for (int it = 0; it < 4; it++) {
        int u = tid + it * 256;          // 0..1023 16-byte units
        int r = u >> 3, s = u & 7;
        const __nv_bfloat16* src = g + (size_t)(row0 + r) * ld + k0 + s * 8;
        CP_ASYNC16(sbase + sw128(r * 128 + s * 16), src);
    }
}

__global__ void __launch_bounds__(256, 1) gemm_nt_tc(
    const __nv_bfloat16* __restrict__ Ah, const __nv_bfloat16* __restrict__ Al,
    const __nv_bfloat16* __restrict__ Bh, const __nv_bfloat16* __restrict__ Bl,
    float* __restrict__ C, __nv_bfloat16* __restrict__ Ch, __nv_bfloat16* __restrict__ Cl,
    int M, int N, int K, int mode, int epi)
{
    extern __shared__ char smem[];
    const int tid = threadIdx.x, wid = tid >> 5, lane = tid & 31;
    const int nb = blockIdx.x, mb = blockIdx.y;
    if (mode == 1 && nb > mb) return;
    const int m0 = mb * 128, n0 = nb * 128;
    const int kend = (mode == 2) ? (m0 + 128 < K ? m0 + 128 : K) : K;
    const int nch = kend >> 6;

    const uint32_t sbase = smem_u32(smem);
    const int wm = wid >> 1;            // 0..3 : 32-row band
    const int wn = wid & 1;             // 0..1 : 64-col band

    float acc[2][8][4];
    #pragma unroll
    for (int mf = 0; mf < 2; mf++)
        #pragma unroll
        for (int nf = 0; nf < 8; nf++)
            #pragma unroll
            for (int c = 0; c < 4; c++) acc[mf][nf][c] = 0.f;

    // preload chunk 0 into buffer 0
    issue_tile64(Ah, m0, K, 0, sbase,              tid);
    issue_tile64(Al, m0, K, 0, sbase + TILE_B,     tid);
    issue_tile64(Bh, n0, K, 0, sbase + 2 * TILE_B, tid);
    issue_tile64(Bl, n0, K, 0, sbase + 3 * TILE_B, tid);
    CP_COMMIT();

    // per-lane ldmatrix addressing
    const int a_row = wm * 32 + (lane & 15);
    const int a_col = ((lane >> 4) & 1) * 16;               // k-half byte offset
    const int b_idx = lane >> 3;                            // 0..3
    const int b_row = wn * 64 + ((b_idx >> 1) * 8) + (lane & 7);
    const int b_col = (b_idx & 1) * 16;

    for (int i = 0; i < nch; i++) {
        if (i + 1 < nch) {
            const uint32_t nbuf = sbase + ((i + 1) & 1) * BUF_B;
            const int k1 = (i + 1) << 6;
            issue_tile64(Ah, m0, K, k1, nbuf,              tid);
            issue_tile64(Al, m0, K, k1, nbuf + TILE_B,     tid);
            issue_tile64(Bh, n0, K, k1, nbuf + 2 * TILE_B, tid);
            issue_tile64(Bl, n0, K, k1, nbuf + 3 * TILE_B, tid);
            CP_COMMIT();
            CP_WAIT1();
        } else {
            CP_WAIT0();
        }
        __syncthreads();

        const uint32_t buf = sbase + (i & 1) * BUF_B;
        #pragma unroll
        for (int ks = 0; ks < 4; ks++) {
            uint32_t ah[2][4], al[2][4], bh[4][4], bl[4][4];
            const int kc = ks * 32;
            ldsm_x4(buf + sw128(a_row * 128 + kc + a_col), ah[0]);
            ldsm_x4(buf + sw128((a_row + 16) * 128 + kc + a_col), ah[1]);
            ldsm_x4(buf + TILE_B + sw128(a_row * 128 + kc + a_col), al[0]);
            ldsm_x4(buf + TILE_B + sw128((a_row + 16) * 128 + kc + a_col), al[1]);
            #pragma unroll
            for (int p = 0; p < 4; p++) {
                ldsm_x4(buf + 2 * TILE_B + sw128((b_row + p * 16) * 128 + kc + b_col), bh[p]);
                ldsm_x4(buf + 3 * TILE_B + sw128((b_row + p * 16) * 128 + kc + b_col), bl[p]);
            }
            #pragma unroll
            for (int mf = 0; mf < 2; mf++)
                #pragma unroll
                for (int p = 0; p < 4; p++)
                    #pragma unroll
                    for (int h = 0; h < 2; h++) {
                        float* d = acc[mf][2 * p + h];
                        mma_bf16(d, ah[mf], &bh[p][2 * h]);   // Ah*Bh
                        mma_bf16(d, ah[mf], &bl[p][2 * h]);   // Ah*Bl
                        mma_bf16(d, al[mf], &bh[p][2 * h]);   // Al*Bh
                    }
        }
        __syncthreads();
    }

    // epilogue: thread owns (m, n) and (m+8, n), n pair (2 cols)
    const int em = m0 + wm * 32 + (lane >> 2);
    const int en = n0 + wn * 64 + (lane & 3) * 2;
    #pragma unroll
    for (int mf = 0; mf < 2; mf++) {
        #pragma unroll
        for (int nf = 0; nf < 8; nf++) {
            const int m = em + mf * 16;
            const int n = en + nf * 8;
            const float* d = acc[mf][nf];
            if (epi == 0) {
                float* r0 = C + (size_t)m * N + n;
                float* r1 = C + (size_t)(m + 8) * N + n;
                r0[0] = d[0]; r0[1] = d[1];
                r1[0] = d[2]; r1[1] = d[3];
            } else {
                #pragma unroll
                for (int hrow = 0; hrow < 2; hrow++) {
                    const int mm = m + hrow * 8;
                    float f0 = d[hrow * 2 + 0], f1 = d[hrow * 2 + 1];
                    __nv_bfloat16 h0 = __float2bfloat16(f0);
                    __nv_bfloat16 h1 = __float2bfloat16(f1);
                    __nv_bfloat162 hv; hv.x = h0; hv.y = h1;
                    __nv_bfloat162 lv;
                    lv.x = __float2bfloat16(f0 - __bfloat162float(h0));
                    lv.y = __float2bfloat16(f1 - __bfloat162float(h1));
                    *(__nv_bfloat162*)(Ch + (size_t)mm * N + n) = hv;
                    *(__nv_bfloat162*)(Cl + (size_t)mm * N + n) = lv;
                }
            }
        }
    }
}

// ============================ fp32 -> hi/lo bf16 split ============================
__global__ __launch_bounds__(256) void split_fp32(const float* __restrict__ in,
                                                  __nv_bfloat16* __restrict__ h,
                                                  __nv_bfloat16* __restrict__ l,
                                                  size_t n4)
{
    size_t i = (size_t)blockIdx.x * 256 + threadIdx.x;
    size_t stride = (size_t)gridDim.x * 256;
    for (; i < n4; i += stride) {
        float4 f = ((const float4*)in)[i];
        __nv_bfloat16 hv[4], lv[4];
        float fv[4] = { f.x, f.y, f.z, f.w };
        #pragma unroll
        for (int c = 0; c < 4; c++) {
            hv[c] = __float2bfloat16(fv[c]);
            lv[c] = __float2bfloat16(fv[c] - __bfloat162float(hv[c]));
        }
        ((uint2*)h)[i] = *(uint2*)hv;
        ((uint2*)l)[i] = *(uint2*)lv;
    }
}

// ============================ softmax + dropout -> hi/lo bf16 =====================
__global__ __launch_bounds__(256) void softmax_dropout_kernel(
    const float* __restrict__ scores, const float* __restrict__ drop_mask,
    __nv_bfloat16* __restrict__ ah, __nv_bfloat16* __restrict__ al)
{
    const int i = blockIdx.x;
    const int tid = threadIdx.x;
    const int nvalid = i + 1;
    const float scale = rsqrtf((float)D_DIM);

    const float* row = scores + (size_t)i * S_TOK;
    const float* mrow = drop_mask + (size_t)i * S_TOK;
    __nv_bfloat16* hrow = ah + (size_t)i * S_TOK;
    __nv_bfloat16* lrow = al + (size_t)i * S_TOK;

    __shared__ float red[256];

    float lmax = -INFINITY;
    for (int j = tid; j < nvalid; j += 256) lmax = fmaxf(lmax, row[j] * scale);
    red[tid] = lmax;
    __syncthreads();
    for (int s = 128; s > 0; s >>= 1) {
        if (tid < s) red[tid] = fmaxf(red[tid], red[tid + s]);
        __syncthreads();
    }
    const float m = red[0];
    __syncthreads();

    float lsum = 0.f;
    for (int j = tid; j < nvalid; j += 256) lsum += __expf(row[j] * scale - m);
    red[tid] = lsum;
    __syncthreads();
    for (int s = 128; s > 0; s >>= 1) {
        if (tid < s) red[tid] += red[tid + s];
        __syncthreads();
    }
    const float inv_z = 1.0f / red[0];

    const int zend = (((i >> 7) + 1) << 7);   // pad to 128-boundary for triangular GEMM
    for (int j = tid; j < zend; j += 256) {
        float out = 0.f;
        if (j < nvalid) out = __expf(row[j] * scale - m) * inv_z * mrow[j];
        __nv_bfloat16 h = __float2bfloat16(out);
        hrow[j] = h;
        lrow[j] = __float2bfloat16(out - __bfloat162float(h));
    }
}

// =================================== launch =======================================
extern "C" void kernel_launch(void* const* d_in, const int* in_sizes, int n_in,
                              void* d_out, int out_size)
{
    const float* x  = (const float*)d_in[0];
    const float* Wq = (const float*)d_in[1];
    const float* Wk = (const float*)d_in[2];
    const float* Wv = (const float*)d_in[3];
    const float* dm = (const float*)d_in[4];
    float* out = (float*)d_out;

    __nv_bfloat16 *xh, *xl, *wqh, *wql, *wkh, *wkl, *wvh, *wvl;
    __nv_bfloat16 *qh, *ql, *kh, *kl, *vth, *vtl, *ah, *al;
    float *sc;
    cudaGetSymbolAddress((void**)&xh,  g_xh);   cudaGetSymbolAddress((void**)&xl,  g_xl);
    cudaGetSymbolAddress((void**)&wqh, g_wqh);  cudaGetSymbolAddress((void**)&wql, g_wql);
    cudaGetSymbolAddress((void**)&wkh, g_wkh);  cudaGetSymbolAddress((void**)&wkl, g_wkl);
    cudaGetSymbolAddress((void**)&wvh, g_wvh);  cudaGetSymbolAddress((void**)&wvl, g_wvl);
    cudaGetSymbolAddress((void**)&qh,  g_qh);   cudaGetSymbolAddress((void**)&ql,  g_ql);
    cudaGetSymbolAddress((void**)&kh,  g_kh);   cudaGetSymbolAddress((void**)&kl,  g_kl);
    cudaGetSymbolAddress((void**)&vth, g_vth);  cudaGetSymbolAddress((void**)&vtl, g_vtl);
    cudaGetSymbolAddress((void**)&ah,  g_ah);   cudaGetSymbolAddress((void**)&al,  g_al);
    cudaGetSymbolAddress((void**)&sc,  g_sc);

    cudaFuncSetAttribute(gemm_nt_tc, cudaFuncAttributeMaxDynamicSharedMemorySize, GEMM_SMEM);

    // 0) split inputs to hi/lo bf16
    split_fp32<<<512, 256>>>(x,  xh,  xl,  (size_t)S_TOK * D_DIM / 4);
    split_fp32<<<512, 256>>>(Wq, wqh, wql, (size_t)D_DIM * D_DIM / 4);
    split_fp32<<<512, 256>>>(Wk, wkh, wkl, (size_t)D_DIM * D_DIM / 4);
    split_fp32<<<512, 256>>>(Wv, wvh, wvl, (size_t)D_DIM * D_DIM / 4);

    // 1) q = x@Wq^T, k = x@Wk^T  (epi -> hi/lo), vT = Wv @ x^T -> [D, S]
    dim3 gProj(D_DIM / 128, S_TOK / 128);
    gemm_nt_tc<<<gProj, 256, GEMM_SMEM>>>(xh, xl, wqh, wql, nullptr, qh, ql,
                                          S_TOK, D_DIM, D_DIM, 0, 1);
    gemm_nt_tc<<<gProj, 256, GEMM_SMEM>>>(xh, xl, wkh, wkl, nullptr, kh, kl,
                                          S_TOK, D_DIM, D_DIM, 0, 1);
    dim3 gVT(S_TOK / 128, D_DIM / 128);
    gemm_nt_tc<<<gVT, 256, GEMM_SMEM>>>(wvh, wvl, xh, xl, nullptr, vth, vtl,
                                        D_DIM, S_TOK, D_DIM, 0, 1);

    // 2) scores = q @ k^T (causal tile-skip, epi fp32)
    dim3 gScore(S_TOK / 128, S_TOK / 128);
    gemm_nt_tc<<<gScore, 256, GEMM_SMEM>>>(qh, ql, kh, kl, sc, nullptr, nullptr,
                                           S_TOK, S_TOK, D_DIM, 1, 0);

    // 3) softmax + dropout -> attn hi/lo (zero-padded to 128-boundary)
    softmax_dropout_kernel<<<S_TOK, 256>>>(sc, dm, ah, al);

    // 4) out = attn @ (vT)^T (triangular K, epi fp32)
    dim3 gOut(D_DIM / 128, S_TOK / 128);
    gemm_nt_tc<<<gOut, 256, GEMM_SMEM>>>(ah, al, vth, vtl, out, nullptr, nullptr,
                                         S_TOK, D_DIM, S_TOK, 2, 0);
}